// round 15
// baseline (speedup 1.0000x reference)
#include <cstdint>
#include <cuda_runtime.h>
#include <cuda_bf16.h>
#include <mma.h>

using namespace nvcuda;

#define BB 128
#define SS 256
#define DD 512
#define HH 1024
#define NCC 128
#define NCTA_REC 128

// ---------------- device scratch ----------------
__device__ __nv_bfloat16  g_Pb[(size_t)SS * BB * 4096];     // input-side preacts, bf16 (no bias)
__device__ __align__(128) unsigned char g_hT2[2][HH * 256]; // transposed+swizzled h: [u][b] bf16, 256B/row
__device__ float          g_hf[BB * HH];                    // final hidden state
__device__ unsigned       g_cnt = 0;                        // init barrier
__device__ unsigned       g_gen = 0;
__device__ unsigned       g_chk[8 * 32];                    // per-chunk producer counters (128B lines)
__device__ __nv_bfloat16  g_embb[(NCC + 1) * DD];           // bf16 embedding
__device__ __nv_bfloat16  g_Wxb[4][(size_t)DD * HH];        // bf16 input weights

__device__ __forceinline__ float sigm(float v) { return 1.0f / (1.0f + expf(-v)); }

// fast approx transcendentals for the scan epilogue (err << bf16 h-quantization)
__device__ __forceinline__ float fsigm(float v) {
    float e, r;
    asm("ex2.approx.f32 %0, %1;" : "=f"(e) : "f"(-v * 1.4426950408889634f));
    asm("rcp.approx.f32 %0, %1;" : "=f"(r) : "f"(1.0f + e));
    return r;
}
__device__ __forceinline__ float ftanh(float v) {
    float r;
    asm("tanh.approx.f32 %0, %1;" : "=f"(r) : "f"(v));
    return r;
}

__device__ __forceinline__ void cp16(unsigned int dst, const void* src) {
    asm volatile("cp.async.cg.shared.global [%0], [%1], 16;\n" :: "r"(dst), "l"(src));
}
__device__ __forceinline__ void cp_commit() { asm volatile("cp.async.commit_group;\n"); }
template <int N> __device__ __forceinline__ void cp_wait() {
    asm volatile("cp.async.wait_group %0;\n" :: "n"(N));
}
__device__ __forceinline__ unsigned ld_acq(const unsigned* p) {
    unsigned v;
    asm volatile("ld.acquire.gpu.global.u32 %0, [%1];" : "=r"(v) : "l"(p) : "memory");
    return v;
}
__device__ __forceinline__ void red_release_add(unsigned* p, unsigned v) {
    asm volatile("red.release.gpu.global.add.u32 [%0], %1;" :: "l"(p), "r"(v) : "memory");
}

// mbarrier helpers
__device__ __forceinline__ void mbar_init(unsigned mbar, unsigned cnt) {
    asm volatile("mbarrier.init.shared.b64 [%0], %1;" :: "r"(mbar), "r"(cnt) : "memory");
}
__device__ __forceinline__ void mbar_expect(unsigned mbar, unsigned bytes) {
    asm volatile("mbarrier.arrive.expect_tx.shared.b64 _, [%0], %1;" :: "r"(mbar), "r"(bytes) : "memory");
}
__device__ __forceinline__ void mbar_arrive(unsigned mbar) {
    asm volatile("mbarrier.arrive.shared.b64 _, [%0];" :: "r"(mbar) : "memory");
}
__device__ __forceinline__ void mbar_wait(unsigned mbar, unsigned phase) {
    asm volatile(
        "{\n\t.reg .pred P1;\n\t"
        "LAB_WAIT_%=:\n\t"
        "mbarrier.try_wait.parity.shared.b64 P1, [%0], %1;\n\t"
        "@P1 bra.uni DONE_%=;\n\t"
        "bra.uni LAB_WAIT_%=;\n\t"
        "DONE_%=:\n\t}"
        :: "r"(mbar), "r"(phase) : "memory");
}
__device__ __forceinline__ void bulk_g2s(unsigned dst, const void* src, unsigned bytes, unsigned mbar) {
    asm volatile("cp.async.bulk.shared::cluster.global.mbarrier::complete_tx::bytes [%0], [%1], %2, [%3];"
                 :: "r"(dst), "l"(src), "r"(bytes), "r"(mbar) : "memory");
}

// init-time grid barrier (atomic; used once per launch)
__device__ __forceinline__ void gridbar()
{
    __syncthreads();
    if (threadIdx.x == 0) {
        __threadfence();
        volatile unsigned* gen = &g_gen;
        unsigned g0 = *gen;
        unsigned arr = atomicAdd(&g_cnt, 1u);
        if (arr == NCTA_REC - 1) {
            g_cnt = 0;
            __threadfence();
            *gen = g0 + 1u;
        } else {
            while (*gen == g0) { }
        }
    }
    __syncthreads();
    __threadfence();
}

// ======================================================================
// Kernel 0: one-time f32 -> bf16 conversion of emb and the 4 input weights
// ======================================================================
__global__ __launch_bounds__(256) void k_convert(
    const float* __restrict__ emb,
    const float* __restrict__ W0, const float* __restrict__ W1,
    const float* __restrict__ W2, const float* __restrict__ W3)
{
    const float* Wsrc[4] = { W0, W1, W2, W3 };
    size_t tid    = (size_t)blockIdx.x * blockDim.x + threadIdx.x;
    size_t stride = (size_t)gridDim.x * blockDim.x;
    const size_t nW4 = (size_t)DD * HH / 4;
    for (size_t e = tid; e < 4 * nW4; e += stride) {
        int g = (int)(e / nW4);
        size_t o = (e % nW4) * 4;
        float4 v = *(const float4*)(Wsrc[g] + o);
        __nv_bfloat16* d = &g_Wxb[g][o];
        d[0] = __float2bfloat16(v.x); d[1] = __float2bfloat16(v.y);
        d[2] = __float2bfloat16(v.z); d[3] = __float2bfloat16(v.w);
    }
    const size_t nE4 = (size_t)(NCC + 1) * DD / 4;
    for (size_t e = tid; e < nE4; e += stride) {
        float4 v = *(const float4*)(emb + e * 4);
        __nv_bfloat16* d = &g_embb[e * 4];
        d[0] = __float2bfloat16(v.x); d[1] = __float2bfloat16(v.y);
        d[2] = __float2bfloat16(v.z); d[3] = __float2bfloat16(v.w);
    }
}

// ======================================================================
// Kernel 1: input projections. 3-stage cp.async (depth-2 prefetch), ONE
// __syncthreads per K-iter (wait -> sync -> issue -> mma). bf16 output.
// cp_wait<1>: with groups {it, it+1} pending at the wait, this guarantees
// group `it` complete (R14 had wait<2> = no-op -> replay race).
// ======================================================================
#define AS_LD 56
#define BS_LD 152
#define K1_STG 3
#define K1_ABYTES (128 * AS_LD * 2)   // 14336
#define K1_BBYTES (32 * BS_LD * 2)    // 9728
#define K1_SMEM   (K1_STG * (K1_ABYTES + K1_BBYTES))  // 72192

__global__ __launch_bounds__(256) void k_input_proj(const int* __restrict__ x)
{
    extern __shared__ __align__(16) unsigned char dyn1[];
    __shared__ int rowidx[128];

    const int t = threadIdx.x, w = t >> 5;
    const int tn = blockIdx.x, tm = blockIdx.y;
    const int n0 = tn * 128, gate = n0 >> 10, h0 = n0 & 1023;
    const __nv_bfloat16* Wb = g_Wxb[gate];

    __nv_bfloat16* As[K1_STG];
    __nv_bfloat16* Bs[K1_STG];
#pragma unroll
    for (int i = 0; i < K1_STG; i++) {
        As[i] = (__nv_bfloat16*)(dyn1 + i * K1_ABYTES);
        Bs[i] = (__nv_bfloat16*)(dyn1 + K1_STG * K1_ABYTES + i * K1_BBYTES);
    }

    if (t < 128) {
        int m = tm * 128 + t;
        int s = m >> 7, b = m & 127;
        rowidx[t] = x[b * SS + s];
    }
    __syncthreads();

    auto issue = [&](int it) {
        int kt = it * 32, buf = it % K1_STG;
        unsigned int Aa = (unsigned int)__cvta_generic_to_shared(As[buf]);
        unsigned int Ba = (unsigned int)__cvta_generic_to_shared(Bs[buf]);
#pragma unroll
        for (int i = 0; i < 2; i++) {
            int e = t + i * 256, r = e >> 2, seg = e & 3;
            cp16(Aa + (r * AS_LD + seg * 8) * 2,
                 g_embb + (size_t)rowidx[r] * DD + kt + seg * 8);
        }
#pragma unroll
        for (int i = 0; i < 2; i++) {
            int e = t + i * 256, r = e >> 4, seg = e & 15;
            cp16(Ba + (r * BS_LD + seg * 8) * 2,
                 Wb + (size_t)(kt + r) * HH + h0 + seg * 8);
        }
    };

    wmma::fragment<wmma::accumulator, 16, 16, 16, float> acc[8];
#pragma unroll
    for (int i = 0; i < 8; i++) wmma::fill_fragment(acc[i], 0.0f);

    issue(0); cp_commit();
    issue(1); cp_commit();

    for (int it = 0; it < 16; it++) {
        const int buf = it % K1_STG;
        cp_wait<1>();          // pending {it, it+1} -> group `it` guaranteed complete
        __syncthreads();       // all threads' copies visible; also guards buffer reuse
        if (it + 2 < 16) issue(it + 2);
        cp_commit();
        const __nv_bfloat16* A = As[buf];
        const __nv_bfloat16* B = Bs[buf];
#pragma unroll
        for (int ks = 0; ks < 2; ks++) {
            wmma::fragment<wmma::matrix_a, 16, 16, 16, __nv_bfloat16, wmma::row_major> af;
            wmma::load_matrix_sync(af, A + (w * 16) * AS_LD + ks * 16, AS_LD);
#pragma unroll
            for (int nb = 0; nb < 8; nb++) {
                wmma::fragment<wmma::matrix_b, 16, 16, 16, __nv_bfloat16, wmma::row_major> bfr;
                wmma::load_matrix_sync(bfr, B + (ks * 16) * BS_LD + nb * 16, BS_LD);
                wmma::mma_sync(acc[nb], af, bfr, acc[nb]);
            }
        }
    }

    // epilogue: stage fp32 in the (now free) prefetch buffers, write bf16 coalesced
    cp_wait<0>();              // drain any straggler copies before reusing dyn1
    __syncthreads();
    float* stage = (float*)dyn1;                 // 128 x 128 f32 = 64KB <= 72KB
#pragma unroll
    for (int nb = 0; nb < 8; nb++)
        wmma::store_matrix_sync(stage + (w * 16) * 128 + nb * 16, acc[nb], 128, wmma::mem_row_major);
    __syncthreads();

    {
        __nv_bfloat16* dst = g_Pb + (size_t)(tm * 128) * 4096 + n0;
        for (int idx = t; idx < 128 * 32; idx += 256) {   // 4 elems per slot
            int row = idx >> 5, c4 = (idx & 31) * 4;
            float4 v = *(float4*)&stage[row * 128 + c4];
            __nv_bfloat162 p0 = __floats2bfloat162_rn(v.x, v.y);
            __nv_bfloat162 p1 = __floats2bfloat162_rn(v.z, v.w);
            *(uint2*)(dst + (size_t)row * 4096 + c4) =
                make_uint2(*(unsigned*)&p0, *(unsigned*)&p1);
        }
    }
}

// ======================================================================
// Kernel 2: persistent recurrent scan (R13 structure), bf16 preact loads.
// ======================================================================
#define WS_LD 1032
#define CHUNK_B 32768

#define SM_MBAR   0      // full[4] @0..31, empty[4] @32..63
#define SM_ABUF   1024
#define SM_WS     (SM_ABUF + 4 * CHUNK_B)      // 132096
#define SM_TOT    (SM_WS + 32 * WS_LD * 2)     // 198144

__global__ void __launch_bounds__(288, 1) k_recur(
    const int*   __restrict__ x,
    const float* __restrict__ Wfh, const float* __restrict__ Wih,
    const float* __restrict__ Wgh, const float* __restrict__ Woh,
    const float* __restrict__ bfp, const float* __restrict__ bip,
    const float* __restrict__ bgp, const float* __restrict__ bop)
{
    extern __shared__ __align__(1024) unsigned char dyn[];
    __nv_bfloat16* Ws = (__nv_bfloat16*)(dyn + SM_WS);

    const unsigned smem0 = (unsigned)__cvta_generic_to_shared(dyn);
    unsigned mbF[4], mbE[4], Abuf[4];
#pragma unroll
    for (int i = 0; i < 4; i++) {
        mbF[i]  = smem0 + SM_MBAR + i * 8;
        mbE[i]  = smem0 + SM_MBAR + 32 + i * 8;
        Abuf[i] = smem0 + SM_ABUF + i * CHUNK_B;
    }

    const int t = threadIdx.x, w = t >> 5, l = t & 31;
    const int c = blockIdx.x, u0 = c * 8;
    const int grp = c >> 4;                    // h-chunk this CTA produces (16 CTAs/chunk)
    const float* Wg[4] = { Wfh, Wih, Wgh, Woh };

    if (t == 0) {
#pragma unroll
        for (int i = 0; i < 4; i++) { mbar_init(mbF[i], 1); mbar_init(mbE[i], 8); }
    }
    asm volatile("fence.proxy.async.shared::cta;" ::: "memory");

    // counter bases (monotonic across replays; read before init gridbar)
    unsigned fb[8];
#pragma unroll
    for (int i = 0; i < 8; i++) fb[i] = *(volatile unsigned*)&g_chk[i * 32];

    // weight slice -> SMEM (bf16, col-major, padded stride)
    for (int e = t; e < 32 * 1024; e += 288) {
        int k = e >> 5, col = e & 31, g = col >> 3, j = col & 7;
        Ws[col * WS_LD + k] = __float2bfloat16(Wg[g][(size_t)k * HH + u0 + j]);
    }
    // zero own 8 rows of hT buffer 0 (8 rows x 256B; 256 threads x 8B)
    if (t < 256)
        *(unsigned long long*)(g_hT2[0] + (u0 + (t >> 5)) * 256 + (t & 31) * 8) = 0ull;

    // ---- fragment-mapped epilogue constants (threads 0..255) ----
    const int r  = w * 16 + (l >> 2);
    const int b1 = r + 8;
    const int uA = u0 + 2 * (l & 3);
    const int uB = uA + 1;
    float2 bF = make_float2(0.f, 0.f), bI = bF, bG = bF, bO = bF;
    if (t < 256) {
        bF = *(const float2*)(bfp + uA);
        bI = *(const float2*)(bip + uA);
        bG = *(const float2*)(bgp + uA);
        bO = *(const float2*)(bop + uA);
    }
    float C0 = 0.f, C1 = 0.f, C2 = 0.f, C3 = 0.f;

    // ldmatrix lane constants (warps 0-7)
    const unsigned a_sw   = (((unsigned)(2 * w + ((l >> 3) & 1)) ^ (unsigned)(l & 7)) << 4);
    const int      a_krow = (l & 7) + ((l >> 4) & 1) * 8;
    const unsigned bbase  = smem0 + SM_WS + ((l & 7) + ((l >> 4) & 1) * 8) * (WS_LD * 2) + ((l >> 3) & 1) * 16;

    // h-store swizzled addresses (4 elements)
    const unsigned hadr0 = (unsigned)(uA * 256 + ((((unsigned)r  >> 3) ^ (uA & 7)) << 4) + (r  & 7) * 2);
    const unsigned hadr1 = (unsigned)(uB * 256 + ((((unsigned)r  >> 3) ^ (uB & 7)) << 4) + (r  & 7) * 2);
    const unsigned hadr2 = (unsigned)(uA * 256 + ((((unsigned)b1 >> 3) ^ (uA & 7)) << 4) + (b1 & 7) * 2);
    const unsigned hadr3 = (unsigned)(uB * 256 + ((((unsigned)b1 >> 3) ^ (uB & 7)) << 4) + (b1 & 7) * 2);

    __syncthreads();
    gridbar();   // zeros + SMEM + mbarriers + counter bases consistent everywhere

    if (t >= 256) {
        // ---------------- producer warp ----------------
        if (t == 256) {
            unsigned q = 0;
            for (int s = 0; s < SS; s++) {
                const unsigned char* hsrc = g_hT2[s & 1];
                const unsigned lvl = (unsigned)s * 128u;   // 16 CTAs x 8 warps per chunk
                for (int cc = 0; cc < 8; cc++, q++) {
                    const int b = q & 3;
                    const unsigned j = q >> 2;
                    if (j) mbar_wait(mbE[b], (j - 1) & 1);    // buffer free
                    if (s) {                                   // producers of chunk cc done step s-1
                        unsigned tgt = fb[cc] + lvl;
                        while ((int)(ld_acq(&g_chk[cc * 32]) - tgt) < 0) { }
                    }
                    mbar_expect(mbF[b], CHUNK_B);
                    bulk_g2s(Abuf[b], hsrc + cc * CHUNK_B, CHUNK_B, mbF[b]);
                }
            }
        }
    } else {
        // ---------------- compute warps (0-7), barrier-free ----------------
        unsigned q = 0;
        for (int s = 0; s < SS; s++) {
            unsigned char* hdst = g_hT2[(s + 1) & 1];

            // prefetch input-side preacts (bf16) + reset masks
            const __nv_bfloat16* PbA = g_Pb + ((size_t)(s * BB + r))  * 4096 + uA;
            const __nv_bfloat16* PbB = g_Pb + ((size_t)(s * BB + b1)) * 4096 + uA;
            unsigned rF0 = *(const unsigned*)(PbA);
            unsigned rI0 = *(const unsigned*)(PbA + 1024);
            unsigned rG0 = *(const unsigned*)(PbA + 2048);
            unsigned rO0 = *(const unsigned*)(PbA + 3072);
            unsigned rF1 = *(const unsigned*)(PbB);
            unsigned rI1 = *(const unsigned*)(PbB + 1024);
            unsigned rG1 = *(const unsigned*)(PbB + 2048);
            unsigned rO1 = *(const unsigned*)(PbB + 3072);
            const float rm0 = (x[r  * SS + s] > 0) ? 1.0f : 0.0f;
            const float rm1 = (x[b1 * SS + s] > 0) ? 1.0f : 0.0f;

            float acc[16];
#pragma unroll
            for (int i = 0; i < 16; i++) acc[i] = 0.0f;

            for (int cc = 0; cc < 8; cc++, q++) {
                const int b = q & 3;
                mbar_wait(mbF[b], (q >> 2) & 1);
                const unsigned Ab = Abuf[b];
#pragma unroll
                for (int kt = 0; kt < 8; kt++) {
                    unsigned aaddr = Ab + (unsigned)((kt * 16 + a_krow) * 256) + a_sw;
                    unsigned a0, a1, a2, a3;
                    asm volatile("ldmatrix.sync.aligned.m8n8.x4.trans.shared.b16 {%0,%1,%2,%3}, [%4];"
                                 : "=r"(a0), "=r"(a1), "=r"(a2), "=r"(a3) : "r"(aaddr));
                    unsigned baddr = bbase + (unsigned)((cc * 8 + kt) * 32);
                    unsigned b0r, b1r, b2r, b3r, b4r, b5r, b6r, b7r;
                    asm volatile("ldmatrix.sync.aligned.m8n8.x4.shared.b16 {%0,%1,%2,%3}, [%4];"
                                 : "=r"(b0r), "=r"(b1r), "=r"(b2r), "=r"(b3r) : "r"(baddr));
                    asm volatile("ldmatrix.sync.aligned.m8n8.x4.shared.b16 {%0,%1,%2,%3}, [%4];"
                                 : "=r"(b4r), "=r"(b5r), "=r"(b6r), "=r"(b7r) : "r"(baddr + 16u * (WS_LD * 2)));

#define MMA4(O, B0, B1) \
                    asm volatile("mma.sync.aligned.m16n8k16.row.col.f32.bf16.bf16.f32 " \
                                 "{%0,%1,%2,%3}, {%4,%5,%6,%7}, {%8,%9}, {%0,%1,%2,%3};" \
                                 : "+f"(acc[O]), "+f"(acc[O+1]), "+f"(acc[O+2]), "+f"(acc[O+3]) \
                                 : "r"(a0), "r"(a1), "r"(a2), "r"(a3), "r"(B0), "r"(B1))
                    MMA4(0,  b0r, b1r);
                    MMA4(4,  b2r, b3r);
                    MMA4(8,  b4r, b5r);
                    MMA4(12, b6r, b7r);
#undef MMA4
                }
                if (l == 0) mbar_arrive(mbE[b]);   // warp done reading buffer b
            }

            // register-resident gate epilogue (approx transcendentals)
            float2 pF0 = __bfloat1622float2(*(__nv_bfloat162*)&rF0);
            float2 pI0 = __bfloat1622float2(*(__nv_bfloat162*)&rI0);
            float2 pG0 = __bfloat1622float2(*(__nv_bfloat162*)&rG0);
            float2 pO0 = __bfloat1622float2(*(__nv_bfloat162*)&rO0);
            float2 pF1 = __bfloat1622float2(*(__nv_bfloat162*)&rF1);
            float2 pI1 = __bfloat1622float2(*(__nv_bfloat162*)&rI1);
            float2 pG1 = __bfloat1622float2(*(__nv_bfloat162*)&rG1);
            float2 pO1 = __bfloat1622float2(*(__nv_bfloat162*)&rO1);

            float f, ii, gg, oo, hv0, hv1, hv2, hv3;

            f  = fsigm(pF0.x + bF.x + acc[0]);
            ii = fsigm(pI0.x + bI.x + acc[4]);
            gg = fsigm(pG0.x + bG.x + acc[8]);
            oo = fsigm(pO0.x + bO.x + acc[12]);
            C0 = (gg * ii + C0 * f) * rm0;  hv0 = oo * ftanh(C0);

            f  = fsigm(pF0.y + bF.y + acc[1]);
            ii = fsigm(pI0.y + bI.y + acc[5]);
            gg = fsigm(pG0.y + bG.y + acc[9]);
            oo = fsigm(pO0.y + bO.y + acc[13]);
            C1 = (gg * ii + C1 * f) * rm0;  hv1 = oo * ftanh(C1);

            f  = fsigm(pF1.x + bF.x + acc[2]);
            ii = fsigm(pI1.x + bI.x + acc[6]);
            gg = fsigm(pG1.x + bG.x + acc[10]);
            oo = fsigm(pO1.x + bO.x + acc[14]);
            C2 = (gg * ii + C2 * f) * rm1;  hv2 = oo * ftanh(C2);

            f  = fsigm(pF1.y + bF.y + acc[3]);
            ii = fsigm(pI1.y + bI.y + acc[7]);
            gg = fsigm(pG1.y + bG.y + acc[11]);
            oo = fsigm(pO1.y + bO.y + acc[15]);
            C3 = (gg * ii + C3 * f) * rm1;  hv3 = oo * ftanh(C3);

            *(__nv_bfloat16*)(hdst + hadr0) = __float2bfloat16(hv0);
            *(__nv_bfloat16*)(hdst + hadr1) = __float2bfloat16(hv1);
            *(__nv_bfloat16*)(hdst + hadr2) = __float2bfloat16(hv2);
            *(__nv_bfloat16*)(hdst + hadr3) = __float2bfloat16(hv3);

            if (s == SS - 1) {
                g_hf[r  * HH + uA] = hv0;
                g_hf[r  * HH + uB] = hv1;
                g_hf[b1 * HH + uA] = hv2;
                g_hf[b1 * HH + uB] = hv3;
            }

            // per-warp publish: warp's h stores done -> release-add on own chunk counter
            __syncwarp();
            if (l == 0 && s < SS - 1)
                red_release_add(&g_chk[grp * 32], 1u);
        }
    }
}

// ======================================================================
// Kernel 3: logits + log_softmax (256 thr, split-K x2, 4 accums — R5 best)
// ======================================================================
__global__ __launch_bounds__(256) void k_final(
    const float* __restrict__ Wph, const float* __restrict__ bp,
    float* __restrict__ out)
{
    __shared__ float h[HH];
    __shared__ float part[NCC];
    __shared__ float red[NCC];
    const int b = blockIdx.x, t = threadIdx.x;
    const int cls = t & 127, half = t >> 7;

    for (int i = t; i < HH; i += 256) h[i] = g_hf[b * HH + i];
    __syncthreads();

    const float* W = Wph + (size_t)(half * 512) * NCC + cls;
    const float* hh = h + half * 512;
    float a0 = 0.f, a1 = 0.f, a2 = 0.f, a3 = 0.f;
#pragma unroll 8
    for (int k = 0; k < 512; k += 4) {
        a0 += hh[k + 0] * W[(size_t)(k + 0) * NCC];
        a1 += hh[k + 1] * W[(size_t)(k + 1) * NCC];
        a2 += hh[k + 2] * W[(size_t)(k + 2) * NCC];
        a3 += hh[k + 3] * W[(size_t)(k + 3) * NCC];
    }
    float p = (a0 + a1) + (a2 + a3);
    if (half) part[cls] = p;
    __syncthreads();

    if (half == 0) p += part[cls] + bp[cls];

    if (t < 128) red[t] = p;
    __syncthreads();
    for (int off = 64; off; off >>= 1) {
        if (t < off) red[t] = fmaxf(red[t], red[t + off]);
        __syncthreads();
    }
    float m = red[0]; __syncthreads();
    if (t < 128) red[t] = expf(p - m);
    __syncthreads();
    for (int off = 64; off; off >>= 1) {
        if (t < off) red[t] += red[t + off];
        __syncthreads();
    }
    if (t < 128) {
        float lse = m + logf(red[0]);
        out[b * NCC + t] = p - lse;
    }
}

// ======================================================================
extern "C" void kernel_launch(void* const* d_in, const int* in_sizes, int n_in,
                              void* d_out, int out_size)
{
    const int*   x   = (const int*)  d_in[0];
    const float* emb = (const float*)d_in[1];
    const float* Wfx = (const float*)d_in[2];
    const float* Wfh = (const float*)d_in[3];
    const float* bf  = (const float*)d_in[4];
    const float* Wix = (const float*)d_in[5];
    const float* Wih = (const float*)d_in[6];
    const float* bi  = (const float*)d_in[7];
    const float* Wgx = (const float*)d_in[8];
    const float* Wgh = (const float*)d_in[9];
    const float* bg  = (const float*)d_in[10];
    const float* Wox = (const float*)d_in[11];
    const float* Woh = (const float*)d_in[12];
    const float* bo  = (const float*)d_in[13];
    const float* Wph = (const float*)d_in[14];
    const float* bp  = (const float*)d_in[15];
    float* out = (float*)d_out;

    static bool attr_set = false;
    if (!attr_set) {
        cudaFuncSetAttribute(k_input_proj, cudaFuncAttributeMaxDynamicSharedMemorySize, K1_SMEM);
        cudaFuncSetAttribute(k_recur,      cudaFuncAttributeMaxDynamicSharedMemorySize, SM_TOT);
        attr_set = true;
    }

    // 0) bf16 pre-conversion
    k_convert<<<512, 256>>>(emb, Wfx, Wix, Wgx, Wox);

    // 1) input-side projections (bf16 output)
    dim3 g1(4096 / 128, (SS * BB) / 128);
    k_input_proj<<<g1, 256, K1_SMEM>>>(x);

    // 2) persistent recurrent scan (warp-specialized, barrier-free loop)
    k_recur<<<NCTA_REC, 288, SM_TOT>>>(x, Wfh, Wih, Wgh, Woh, bf, bi, bg, bo);

    // 3) final projection + log_softmax
    k_final<<<BB, 256>>>(Wph, bp, out);
}

// round 16
// speedup vs baseline: 1.5232x; 1.5232x over previous
#include <cstdint>
#include <cuda_runtime.h>
#include <cuda_bf16.h>
#include <mma.h>

using namespace nvcuda;

#define BB 128
#define SS 256
#define DD 512
#define HH 1024
#define NCC 128
#define NCTA_REC 128

// ---------------- device scratch ----------------
__device__ float          g_P[(size_t)SS * BB * 4096];      // input-side preacts (no bias)
__device__ __align__(128) unsigned char g_hT2[2][HH * 256]; // transposed+swizzled h: [u][b] bf16, 256B/row
__device__ float          g_hf[BB * HH];                    // final hidden state
__device__ unsigned       g_cnt = 0;                        // init barrier
__device__ unsigned       g_gen = 0;
__device__ unsigned       g_chk[8 * 32];                    // per-chunk producer counters (128B lines)
__device__ __nv_bfloat16  g_embb[(NCC + 1) * DD];           // bf16 embedding
__device__ __nv_bfloat16  g_Wxb[4][(size_t)DD * HH];        // bf16 input weights

__device__ __forceinline__ float sigm(float v) { return 1.0f / (1.0f + expf(-v)); }

// fast approx transcendentals for the scan epilogue (err << bf16 h-quantization)
__device__ __forceinline__ float fsigm(float v) {
    float e, r;
    asm("ex2.approx.f32 %0, %1;" : "=f"(e) : "f"(-v * 1.4426950408889634f));
    asm("rcp.approx.f32 %0, %1;" : "=f"(r) : "f"(1.0f + e));
    return r;
}
__device__ __forceinline__ float ftanh(float v) {
    float r;
    asm("tanh.approx.f32 %0, %1;" : "=f"(r) : "f"(v));
    return r;
}

__device__ __forceinline__ void cp16(unsigned int dst, const void* src) {
    asm volatile("cp.async.cg.shared.global [%0], [%1], 16;\n" :: "r"(dst), "l"(src));
}
__device__ __forceinline__ void cp_commit() { asm volatile("cp.async.commit_group;\n"); }
template <int N> __device__ __forceinline__ void cp_wait() {
    asm volatile("cp.async.wait_group %0;\n" :: "n"(N));
}
__device__ __forceinline__ unsigned ld_acq(const unsigned* p) {
    unsigned v;
    asm volatile("ld.acquire.gpu.global.u32 %0, [%1];" : "=r"(v) : "l"(p) : "memory");
    return v;
}
__device__ __forceinline__ void red_release_add(unsigned* p, unsigned v) {
    asm volatile("red.release.gpu.global.add.u32 [%0], %1;" :: "l"(p), "r"(v) : "memory");
}

// mbarrier helpers
__device__ __forceinline__ void mbar_init(unsigned mbar, unsigned cnt) {
    asm volatile("mbarrier.init.shared.b64 [%0], %1;" :: "r"(mbar), "r"(cnt) : "memory");
}
__device__ __forceinline__ void mbar_expect(unsigned mbar, unsigned bytes) {
    asm volatile("mbarrier.arrive.expect_tx.shared.b64 _, [%0], %1;" :: "r"(mbar), "r"(bytes) : "memory");
}
__device__ __forceinline__ void mbar_arrive(unsigned mbar) {
    asm volatile("mbarrier.arrive.shared.b64 _, [%0];" :: "r"(mbar) : "memory");
}
__device__ __forceinline__ void mbar_wait(unsigned mbar, unsigned phase) {
    asm volatile(
        "{\n\t.reg .pred P1;\n\t"
        "LAB_WAIT_%=:\n\t"
        "mbarrier.try_wait.parity.shared.b64 P1, [%0], %1;\n\t"
        "@P1 bra.uni DONE_%=;\n\t"
        "bra.uni LAB_WAIT_%=;\n\t"
        "DONE_%=:\n\t}"
        :: "r"(mbar), "r"(phase) : "memory");
}
__device__ __forceinline__ void bulk_g2s(unsigned dst, const void* src, unsigned bytes, unsigned mbar) {
    asm volatile("cp.async.bulk.shared::cluster.global.mbarrier::complete_tx::bytes [%0], [%1], %2, [%3];"
                 :: "r"(dst), "l"(src), "r"(bytes), "r"(mbar) : "memory");
}

// init-time grid barrier (atomic; used once per launch)
__device__ __forceinline__ void gridbar()
{
    __syncthreads();
    if (threadIdx.x == 0) {
        __threadfence();
        volatile unsigned* gen = &g_gen;
        unsigned g0 = *gen;
        unsigned arr = atomicAdd(&g_cnt, 1u);
        if (arr == NCTA_REC - 1) {
            g_cnt = 0;
            __threadfence();
            *gen = g0 + 1u;
        } else {
            while (*gen == g0) { }
        }
    }
    __syncthreads();
    __threadfence();
}

// ======================================================================
// Kernel 0: one-time f32 -> bf16 conversion of emb and the 4 input weights
// ======================================================================
__global__ __launch_bounds__(256) void k_convert(
    const float* __restrict__ emb,
    const float* __restrict__ W0, const float* __restrict__ W1,
    const float* __restrict__ W2, const float* __restrict__ W3)
{
    const float* Wsrc[4] = { W0, W1, W2, W3 };
    size_t tid    = (size_t)blockIdx.x * blockDim.x + threadIdx.x;
    size_t stride = (size_t)gridDim.x * blockDim.x;
    const size_t nW4 = (size_t)DD * HH / 4;
    for (size_t e = tid; e < 4 * nW4; e += stride) {
        int g = (int)(e / nW4);
        size_t o = (e % nW4) * 4;
        float4 v = *(const float4*)(Wsrc[g] + o);
        __nv_bfloat16* d = &g_Wxb[g][o];
        d[0] = __float2bfloat16(v.x); d[1] = __float2bfloat16(v.y);
        d[2] = __float2bfloat16(v.z); d[3] = __float2bfloat16(v.w);
    }
    const size_t nE4 = (size_t)(NCC + 1) * DD / 4;
    for (size_t e = tid; e < nE4; e += stride) {
        float4 v = *(const float4*)(emb + e * 4);
        __nv_bfloat16* d = &g_embb[e * 4];
        d[0] = __float2bfloat16(v.x); d[1] = __float2bfloat16(v.y);
        d[2] = __float2bfloat16(v.z); d[3] = __float2bfloat16(v.w);
    }
}

// ======================================================================
// Kernel 1: input projections (double-buffered cp.async + wmma) — R13 exact
// ======================================================================
#define AS_LD 56
#define BS_LD 152

__global__ __launch_bounds__(256) void k_input_proj(const int* __restrict__ x)
{
    __shared__ __align__(16) __nv_bfloat16 As[2][128 * AS_LD];
    __shared__ __align__(16) __nv_bfloat16 Bs[2][32 * BS_LD];
    __shared__ int rowidx[128];

    const int t = threadIdx.x, w = t >> 5;
    const int tn = blockIdx.x, tm = blockIdx.y;
    const int n0 = tn * 128, gate = n0 >> 10, h0 = n0 & 1023;
    const __nv_bfloat16* Wb = g_Wxb[gate];

    if (t < 128) {
        int m = tm * 128 + t;
        int s = m >> 7, b = m & 127;
        rowidx[t] = x[b * SS + s];
    }
    __syncthreads();

    auto issue = [&](int it) {
        int kt = it * 32;
        unsigned int Aa = (unsigned int)__cvta_generic_to_shared(As[it & 1]);
        unsigned int Ba = (unsigned int)__cvta_generic_to_shared(Bs[it & 1]);
#pragma unroll
        for (int i = 0; i < 2; i++) {
            int e = t + i * 256, r = e >> 2, seg = e & 3;
            cp16(Aa + (r * AS_LD + seg * 8) * 2,
                 g_embb + (size_t)rowidx[r] * DD + kt + seg * 8);
        }
#pragma unroll
        for (int i = 0; i < 2; i++) {
            int e = t + i * 256, r = e >> 4, seg = e & 15;
            cp16(Ba + (r * BS_LD + seg * 8) * 2,
                 Wb + (size_t)(kt + r) * HH + h0 + seg * 8);
        }
    };

    wmma::fragment<wmma::accumulator, 16, 16, 16, float> acc[8];
#pragma unroll
    for (int i = 0; i < 8; i++) wmma::fill_fragment(acc[i], 0.0f);

    issue(0); cp_commit();
    for (int it = 0; it < 16; it++) {
        if (it < 15) issue(it + 1);
        cp_commit();
        cp_wait<1>();
        __syncthreads();
        const __nv_bfloat16* A = As[it & 1];
        const __nv_bfloat16* B = Bs[it & 1];
#pragma unroll
        for (int ks = 0; ks < 2; ks++) {
            wmma::fragment<wmma::matrix_a, 16, 16, 16, __nv_bfloat16, wmma::row_major> af;
            wmma::load_matrix_sync(af, A + (w * 16) * AS_LD + ks * 16, AS_LD);
#pragma unroll
            for (int nb = 0; nb < 8; nb++) {
                wmma::fragment<wmma::matrix_b, 16, 16, 16, __nv_bfloat16, wmma::row_major> bfr;
                wmma::load_matrix_sync(bfr, B + (ks * 16) * BS_LD + nb * 16, BS_LD);
                wmma::mma_sync(acc[nb], af, bfr, acc[nb]);
            }
        }
        __syncthreads();
    }

    size_t base = (size_t)(tm * 128 + w * 16) * 4096 + n0;
#pragma unroll
    for (int nb = 0; nb < 8; nb++)
        wmma::store_matrix_sync(g_P + base + nb * 16, acc[nb], 4096, wmma::mem_row_major);
}

// ======================================================================
// Kernel 2: persistent recurrent scan — R13 exact (warp-specialized,
// barrier-free compute loop, register-resident epilogue).
// ======================================================================
#define WS_LD 1032
#define CHUNK_B 32768

#define SM_MBAR   0      // full[4] @0..31, empty[4] @32..63
#define SM_ABUF   1024
#define SM_WS     (SM_ABUF + 4 * CHUNK_B)      // 132096
#define SM_TOT    (SM_WS + 32 * WS_LD * 2)     // 198144

__global__ void __launch_bounds__(288, 1) k_recur(
    const int*   __restrict__ x,
    const float* __restrict__ Wfh, const float* __restrict__ Wih,
    const float* __restrict__ Wgh, const float* __restrict__ Woh,
    const float* __restrict__ bfp, const float* __restrict__ bip,
    const float* __restrict__ bgp, const float* __restrict__ bop)
{
    extern __shared__ __align__(1024) unsigned char dyn[];
    __nv_bfloat16* Ws = (__nv_bfloat16*)(dyn + SM_WS);

    const unsigned smem0 = (unsigned)__cvta_generic_to_shared(dyn);
    unsigned mbF[4], mbE[4], Abuf[4];
#pragma unroll
    for (int i = 0; i < 4; i++) {
        mbF[i]  = smem0 + SM_MBAR + i * 8;
        mbE[i]  = smem0 + SM_MBAR + 32 + i * 8;
        Abuf[i] = smem0 + SM_ABUF + i * CHUNK_B;
    }

    const int t = threadIdx.x, w = t >> 5, l = t & 31;
    const int c = blockIdx.x, u0 = c * 8;
    const int grp = c >> 4;                    // h-chunk this CTA produces (16 CTAs/chunk)
    const float* Wg[4] = { Wfh, Wih, Wgh, Woh };

    if (t == 0) {
#pragma unroll
        for (int i = 0; i < 4; i++) { mbar_init(mbF[i], 1); mbar_init(mbE[i], 8); }
    }
    asm volatile("fence.proxy.async.shared::cta;" ::: "memory");

    // counter bases (monotonic across replays; read before init gridbar)
    unsigned fb[8];
#pragma unroll
    for (int i = 0; i < 8; i++) fb[i] = *(volatile unsigned*)&g_chk[i * 32];

    // weight slice -> SMEM (bf16, col-major, padded stride)
    for (int e = t; e < 32 * 1024; e += 288) {
        int k = e >> 5, col = e & 31, g = col >> 3, j = col & 7;
        Ws[col * WS_LD + k] = __float2bfloat16(Wg[g][(size_t)k * HH + u0 + j]);
    }
    // zero own 8 rows of hT buffer 0 (8 rows x 256B; 256 threads x 8B)
    if (t < 256)
        *(unsigned long long*)(g_hT2[0] + (u0 + (t >> 5)) * 256 + (t & 31) * 8) = 0ull;

    // ---- fragment-mapped epilogue constants (threads 0..255) ----
    const int r  = w * 16 + (l >> 2);
    const int b1 = r + 8;
    const int uA = u0 + 2 * (l & 3);
    const int uB = uA + 1;
    float2 bF = make_float2(0.f, 0.f), bI = bF, bG = bF, bO = bF;
    if (t < 256) {
        bF = *(const float2*)(bfp + uA);
        bI = *(const float2*)(bip + uA);
        bG = *(const float2*)(bgp + uA);
        bO = *(const float2*)(bop + uA);
    }
    float C0 = 0.f, C1 = 0.f, C2 = 0.f, C3 = 0.f;

    // ldmatrix lane constants (warps 0-7)
    const unsigned a_sw   = (((unsigned)(2 * w + ((l >> 3) & 1)) ^ (unsigned)(l & 7)) << 4);
    const int      a_krow = (l & 7) + ((l >> 4) & 1) * 8;
    const unsigned bbase  = smem0 + SM_WS + ((l & 7) + ((l >> 4) & 1) * 8) * (WS_LD * 2) + ((l >> 3) & 1) * 16;

    // h-store swizzled addresses (4 elements)
    const unsigned hadr0 = (unsigned)(uA * 256 + ((((unsigned)r  >> 3) ^ (uA & 7)) << 4) + (r  & 7) * 2);
    const unsigned hadr1 = (unsigned)(uB * 256 + ((((unsigned)r  >> 3) ^ (uB & 7)) << 4) + (r  & 7) * 2);
    const unsigned hadr2 = (unsigned)(uA * 256 + ((((unsigned)b1 >> 3) ^ (uA & 7)) << 4) + (b1 & 7) * 2);
    const unsigned hadr3 = (unsigned)(uB * 256 + ((((unsigned)b1 >> 3) ^ (uB & 7)) << 4) + (b1 & 7) * 2);

    __syncthreads();
    gridbar();   // zeros + SMEM + mbarriers + counter bases consistent everywhere

    if (t >= 256) {
        // ---------------- producer warp ----------------
        if (t == 256) {
            unsigned q = 0;
            for (int s = 0; s < SS; s++) {
                const unsigned char* hsrc = g_hT2[s & 1];
                const unsigned lvl = (unsigned)s * 128u;   // 16 CTAs x 8 warps per chunk
                for (int cc = 0; cc < 8; cc++, q++) {
                    const int b = q & 3;
                    const unsigned j = q >> 2;
                    if (j) mbar_wait(mbE[b], (j - 1) & 1);    // buffer free
                    if (s) {                                   // producers of chunk cc done step s-1
                        unsigned tgt = fb[cc] + lvl;
                        while ((int)(ld_acq(&g_chk[cc * 32]) - tgt) < 0) { }
                    }
                    mbar_expect(mbF[b], CHUNK_B);
                    bulk_g2s(Abuf[b], hsrc + cc * CHUNK_B, CHUNK_B, mbF[b]);
                }
            }
        }
    } else {
        // ---------------- compute warps (0-7), barrier-free ----------------
        unsigned q = 0;
        for (int s = 0; s < SS; s++) {
            unsigned char* hdst = g_hT2[(s + 1) & 1];

            // prefetch input-side preacts + reset masks (fragment mapping)
            const float* PbA = g_P + ((size_t)(s * BB + r))  * 4096 + uA;
            const float* PbB = g_P + ((size_t)(s * BB + b1)) * 4096 + uA;
            float2 pF0 = *(const float2*)(PbA);
            float2 pI0 = *(const float2*)(PbA + 1024);
            float2 pG0 = *(const float2*)(PbA + 2048);
            float2 pO0 = *(const float2*)(PbA + 3072);
            float2 pF1 = *(const float2*)(PbB);
            float2 pI1 = *(const float2*)(PbB + 1024);
            float2 pG1 = *(const float2*)(PbB + 2048);
            float2 pO1 = *(const float2*)(PbB + 3072);
            const float rm0 = (x[r  * SS + s] > 0) ? 1.0f : 0.0f;
            const float rm1 = (x[b1 * SS + s] > 0) ? 1.0f : 0.0f;

            float acc[16];
#pragma unroll
            for (int i = 0; i < 16; i++) acc[i] = 0.0f;

            for (int cc = 0; cc < 8; cc++, q++) {
                const int b = q & 3;
                mbar_wait(mbF[b], (q >> 2) & 1);
                const unsigned Ab = Abuf[b];
#pragma unroll
                for (int kt = 0; kt < 8; kt++) {
                    unsigned aaddr = Ab + (unsigned)((kt * 16 + a_krow) * 256) + a_sw;
                    unsigned a0, a1, a2, a3;
                    asm volatile("ldmatrix.sync.aligned.m8n8.x4.trans.shared.b16 {%0,%1,%2,%3}, [%4];"
                                 : "=r"(a0), "=r"(a1), "=r"(a2), "=r"(a3) : "r"(aaddr));
                    unsigned baddr = bbase + (unsigned)((cc * 8 + kt) * 32);
                    unsigned b0r, b1r, b2r, b3r, b4r, b5r, b6r, b7r;
                    asm volatile("ldmatrix.sync.aligned.m8n8.x4.shared.b16 {%0,%1,%2,%3}, [%4];"
                                 : "=r"(b0r), "=r"(b1r), "=r"(b2r), "=r"(b3r) : "r"(baddr));
                    asm volatile("ldmatrix.sync.aligned.m8n8.x4.shared.b16 {%0,%1,%2,%3}, [%4];"
                                 : "=r"(b4r), "=r"(b5r), "=r"(b6r), "=r"(b7r) : "r"(baddr + 16u * (WS_LD * 2)));

#define MMA4(O, B0, B1) \
                    asm volatile("mma.sync.aligned.m16n8k16.row.col.f32.bf16.bf16.f32 " \
                                 "{%0,%1,%2,%3}, {%4,%5,%6,%7}, {%8,%9}, {%0,%1,%2,%3};" \
                                 : "+f"(acc[O]), "+f"(acc[O+1]), "+f"(acc[O+2]), "+f"(acc[O+3]) \
                                 : "r"(a0), "r"(a1), "r"(a2), "r"(a3), "r"(B0), "r"(B1))
                    MMA4(0,  b0r, b1r);
                    MMA4(4,  b2r, b3r);
                    MMA4(8,  b4r, b5r);
                    MMA4(12, b6r, b7r);
#undef MMA4
                }
                if (l == 0) mbar_arrive(mbE[b]);   // warp done reading buffer b
            }

            // register-resident gate epilogue (approx transcendentals)
            float f, ii, gg, oo, hv0, hv1, hv2, hv3;

            f  = fsigm(pF0.x + bF.x + acc[0]);
            ii = fsigm(pI0.x + bI.x + acc[4]);
            gg = fsigm(pG0.x + bG.x + acc[8]);
            oo = fsigm(pO0.x + bO.x + acc[12]);
            C0 = (gg * ii + C0 * f) * rm0;  hv0 = oo * ftanh(C0);

            f  = fsigm(pF0.y + bF.y + acc[1]);
            ii = fsigm(pI0.y + bI.y + acc[5]);
            gg = fsigm(pG0.y + bG.y + acc[9]);
            oo = fsigm(pO0.y + bO.y + acc[13]);
            C1 = (gg * ii + C1 * f) * rm0;  hv1 = oo * ftanh(C1);

            f  = fsigm(pF1.x + bF.x + acc[2]);
            ii = fsigm(pI1.x + bI.x + acc[6]);
            gg = fsigm(pG1.x + bG.x + acc[10]);
            oo = fsigm(pO1.x + bO.x + acc[14]);
            C2 = (gg * ii + C2 * f) * rm1;  hv2 = oo * ftanh(C2);

            f  = fsigm(pF1.y + bF.y + acc[3]);
            ii = fsigm(pI1.y + bI.y + acc[7]);
            gg = fsigm(pG1.y + bG.y + acc[11]);
            oo = fsigm(pO1.y + bO.y + acc[15]);
            C3 = (gg * ii + C3 * f) * rm1;  hv3 = oo * ftanh(C3);

            *(__nv_bfloat16*)(hdst + hadr0) = __float2bfloat16(hv0);
            *(__nv_bfloat16*)(hdst + hadr1) = __float2bfloat16(hv1);
            *(__nv_bfloat16*)(hdst + hadr2) = __float2bfloat16(hv2);
            *(__nv_bfloat16*)(hdst + hadr3) = __float2bfloat16(hv3);

            if (s == SS - 1) {
                g_hf[r  * HH + uA] = hv0;
                g_hf[r  * HH + uB] = hv1;
                g_hf[b1 * HH + uA] = hv2;
                g_hf[b1 * HH + uB] = hv3;
            }

            // per-warp publish: warp's h stores done -> release-add on own chunk counter
            __syncwarp();
            if (l == 0 && s < SS - 1)
                red_release_add(&g_chk[grp * 32], 1u);
        }
    }
}

// ======================================================================
// Kernel 3: logits + log_softmax — 512 thr, split-K x4, 4 accums each.
// ======================================================================
__global__ __launch_bounds__(512) void k_final(
    const float* __restrict__ Wph, const float* __restrict__ bp,
    float* __restrict__ out)
{
    __shared__ float h[HH];
    __shared__ float part[3][NCC];
    __shared__ float red[NCC];
    const int b = blockIdx.x, t = threadIdx.x;
    const int cls = t & 127, quarter = t >> 7;

    for (int i = t; i < HH; i += 512) h[i] = g_hf[b * HH + i];
    __syncthreads();

    const float* W = Wph + (size_t)(quarter * 256) * NCC + cls;
    const float* hh = h + quarter * 256;
    float a0 = 0.f, a1 = 0.f, a2 = 0.f, a3 = 0.f;
#pragma unroll 8
    for (int k = 0; k < 256; k += 4) {
        a0 += hh[k + 0] * W[(size_t)(k + 0) * NCC];
        a1 += hh[k + 1] * W[(size_t)(k + 1) * NCC];
        a2 += hh[k + 2] * W[(size_t)(k + 2) * NCC];
        a3 += hh[k + 3] * W[(size_t)(k + 3) * NCC];
    }
    float p = (a0 + a1) + (a2 + a3);
    if (quarter) part[quarter - 1][cls] = p;
    __syncthreads();

    if (quarter == 0)
        p += part[0][cls] + part[1][cls] + part[2][cls] + bp[cls];

    if (t < 128) red[t] = p;
    __syncthreads();
    for (int off = 64; off; off >>= 1) {
        if (t < off) red[t] = fmaxf(red[t], red[t + off]);
        __syncthreads();
    }
    float m = red[0]; __syncthreads();
    if (t < 128) red[t] = expf(p - m);
    __syncthreads();
    for (int off = 64; off; off >>= 1) {
        if (t < off) red[t] += red[t + off];
        __syncthreads();
    }
    if (t < 128) {
        float lse = m + logf(red[0]);
        out[b * NCC + t] = p - lse;
    }
}

// ======================================================================
extern "C" void kernel_launch(void* const* d_in, const int* in_sizes, int n_in,
                              void* d_out, int out_size)
{
    const int*   x   = (const int*)  d_in[0];
    const float* emb = (const float*)d_in[1];
    const float* Wfx = (const float*)d_in[2];
    const float* Wfh = (const float*)d_in[3];
    const float* bf  = (const float*)d_in[4];
    const float* Wix = (const float*)d_in[5];
    const float* Wih = (const float*)d_in[6];
    const float* bi  = (const float*)d_in[7];
    const float* Wgx = (const float*)d_in[8];
    const float* Wgh = (const float*)d_in[9];
    const float* bg  = (const float*)d_in[10];
    const float* Wox = (const float*)d_in[11];
    const float* Woh = (const float*)d_in[12];
    const float* bo  = (const float*)d_in[13];
    const float* Wph = (const float*)d_in[14];
    const float* bp  = (const float*)d_in[15];
    float* out = (float*)d_out;

    static bool attr_set = false;
    if (!attr_set) {
        cudaFuncSetAttribute(k_recur, cudaFuncAttributeMaxDynamicSharedMemorySize, SM_TOT);
        attr_set = true;
    }

    // 0) bf16 pre-conversion
    k_convert<<<512, 256>>>(emb, Wfx, Wix, Wgx, Wox);

    // 1) input-side projections
    dim3 g1(4096 / 128, (SS * BB) / 128);
    k_input_proj<<<g1, 256>>>(x);

    // 2) persistent recurrent scan (warp-specialized, barrier-free loop)
    k_recur<<<NCTA_REC, 288, SM_TOT>>>(x, Wfh, Wih, Wgh, Woh, bf, bi, bg, bo);

    // 3) final projection + log_softmax
    k_final<<<BB, 512>>>(Wph, bp, out);
}

// round 17
// speedup vs baseline: 2.1785x; 1.4302x over previous
#include <cstdint>
#include <cuda_runtime.h>
#include <cuda_bf16.h>
#include <mma.h>

using namespace nvcuda;

#define BB 128
#define SS 256
#define DD 512
#define HH 1024
#define NCC 128
#define NCTA_REC 128

// ---------------- device scratch ----------------
__device__ float          g_Ep[(NCC + 1) * 4096];           // E'[vocab][4 gates x 1024], fp32, L2-resident
__device__ __align__(128) unsigned char g_hT2[2][HH * 256]; // transposed+swizzled h: [u][b] bf16, 256B/row
__device__ float          g_hf[BB * HH];                    // final hidden state
__device__ unsigned       g_cnt = 0;                        // init barrier
__device__ unsigned       g_gen = 0;
__device__ unsigned       g_chk[8 * 32];                    // per-chunk producer counters (128B lines)

// fast approx transcendentals for the scan epilogue (err << bf16 h-quantization)
__device__ __forceinline__ float fsigm(float v) {
    float e, r;
    asm("ex2.approx.f32 %0, %1;" : "=f"(e) : "f"(-v * 1.4426950408889634f));
    asm("rcp.approx.f32 %0, %1;" : "=f"(r) : "f"(1.0f + e));
    return r;
}
__device__ __forceinline__ float ftanh(float v) {
    float r;
    asm("tanh.approx.f32 %0, %1;" : "=f"(r) : "f"(v));
    return r;
}

__device__ __forceinline__ unsigned ld_acq(const unsigned* p) {
    unsigned v;
    asm volatile("ld.acquire.gpu.global.u32 %0, [%1];" : "=r"(v) : "l"(p) : "memory");
    return v;
}
__device__ __forceinline__ void red_release_add(unsigned* p, unsigned v) {
    asm volatile("red.release.gpu.global.add.u32 [%0], %1;" :: "l"(p), "r"(v) : "memory");
}

// mbarrier helpers
__device__ __forceinline__ void mbar_init(unsigned mbar, unsigned cnt) {
    asm volatile("mbarrier.init.shared.b64 [%0], %1;" :: "r"(mbar), "r"(cnt) : "memory");
}
__device__ __forceinline__ void mbar_expect(unsigned mbar, unsigned bytes) {
    asm volatile("mbarrier.arrive.expect_tx.shared.b64 _, [%0], %1;" :: "r"(mbar), "r"(bytes) : "memory");
}
__device__ __forceinline__ void mbar_arrive(unsigned mbar) {
    asm volatile("mbarrier.arrive.shared.b64 _, [%0];" :: "r"(mbar) : "memory");
}
__device__ __forceinline__ void mbar_wait(unsigned mbar, unsigned phase) {
    asm volatile(
        "{\n\t.reg .pred P1;\n\t"
        "LAB_WAIT_%=:\n\t"
        "mbarrier.try_wait.parity.shared.b64 P1, [%0], %1;\n\t"
        "@P1 bra.uni DONE_%=;\n\t"
        "bra.uni LAB_WAIT_%=;\n\t"
        "DONE_%=:\n\t}"
        :: "r"(mbar), "r"(phase) : "memory");
}
__device__ __forceinline__ void bulk_g2s(unsigned dst, const void* src, unsigned bytes, unsigned mbar) {
    asm volatile("cp.async.bulk.shared::cluster.global.mbarrier::complete_tx::bytes [%0], [%1], %2, [%3];"
                 :: "r"(dst), "l"(src), "r"(bytes), "r"(mbar) : "memory");
}

// init-time grid barrier (atomic; used once per launch)
__device__ __forceinline__ void gridbar()
{
    __syncthreads();
    if (threadIdx.x == 0) {
        __threadfence();
        volatile unsigned* gen = &g_gen;
        unsigned g0 = *gen;
        unsigned arr = atomicAdd(&g_cnt, 1u);
        if (arr == NCTA_REC - 1) {
            g_cnt = 0;
            __threadfence();
            *gen = g0 + 1u;
        } else {
            while (*gen == g0) { }
        }
    }
    __syncthreads();
    __threadfence();
}

// ======================================================================
// Kernel 1: E'[v] = emb[v] @ [Wfx|Wix|Wgx|Wox]  (129 x 4096, fp32)
// 128 blocks x 32 cols; W column-slice cached in SMEM (64KB).
// ======================================================================
__global__ __launch_bounds__(256) void k_eprime(
    const float* __restrict__ emb,
    const float* __restrict__ W0, const float* __restrict__ W1,
    const float* __restrict__ W2, const float* __restrict__ W3)
{
    extern __shared__ float Ws[];                 // [512][32]
    const int t = threadIdx.x;
    const int col0 = blockIdx.x * 32;
    const int gate = col0 >> 10, hcol = col0 & 1023;
    const float* W = (gate == 0) ? W0 : (gate == 1) ? W1 : (gate == 2) ? W2 : W3;

    for (int e = t; e < 512 * 32; e += 256) {
        int k = e >> 5, c = e & 31;
        Ws[e] = W[(size_t)k * HH + hcol + c];
    }
    __syncthreads();

    for (int o = t; o < (NCC + 1) * 32; o += 256) {
        int r = o >> 5, c = o & 31;
        const float* er = emb + (size_t)r * DD;
        float a0 = 0.f, a1 = 0.f, a2 = 0.f, a3 = 0.f;
#pragma unroll 8
        for (int k = 0; k < DD; k += 4) {
            a0 += er[k + 0] * Ws[(k + 0) * 32 + c];
            a1 += er[k + 1] * Ws[(k + 1) * 32 + c];
            a2 += er[k + 2] * Ws[(k + 2) * 32 + c];
            a3 += er[k + 3] * Ws[(k + 3) * 32 + c];
        }
        g_Ep[(size_t)r * 4096 + col0 + c] = (a0 + a1) + (a2 + a3);
    }
}

// ======================================================================
// Kernel 2: persistent recurrent scan — R16 structure; preacts gathered
// from the L2-resident E' table (indexed by token id) instead of g_P.
// ======================================================================
#define WS_LD 1032
#define CHUNK_B 32768

#define SM_MBAR   0      // full[4] @0..31, empty[4] @32..63
#define SM_ABUF   1024
#define SM_WS     (SM_ABUF + 4 * CHUNK_B)      // 132096
#define SM_TOT    (SM_WS + 32 * WS_LD * 2)     // 198144

__global__ void __launch_bounds__(288, 1) k_recur(
    const int*   __restrict__ x,
    const float* __restrict__ Wfh, const float* __restrict__ Wih,
    const float* __restrict__ Wgh, const float* __restrict__ Woh,
    const float* __restrict__ bfp, const float* __restrict__ bip,
    const float* __restrict__ bgp, const float* __restrict__ bop)
{
    extern __shared__ __align__(1024) unsigned char dyn[];
    __nv_bfloat16* Ws = (__nv_bfloat16*)(dyn + SM_WS);

    const unsigned smem0 = (unsigned)__cvta_generic_to_shared(dyn);
    unsigned mbF[4], mbE[4], Abuf[4];
#pragma unroll
    for (int i = 0; i < 4; i++) {
        mbF[i]  = smem0 + SM_MBAR + i * 8;
        mbE[i]  = smem0 + SM_MBAR + 32 + i * 8;
        Abuf[i] = smem0 + SM_ABUF + i * CHUNK_B;
    }

    const int t = threadIdx.x, w = t >> 5, l = t & 31;
    const int c = blockIdx.x, u0 = c * 8;
    const int grp = c >> 4;                    // h-chunk this CTA produces (16 CTAs/chunk)
    const float* Wg[4] = { Wfh, Wih, Wgh, Woh };

    if (t == 0) {
#pragma unroll
        for (int i = 0; i < 4; i++) { mbar_init(mbF[i], 1); mbar_init(mbE[i], 8); }
    }
    asm volatile("fence.proxy.async.shared::cta;" ::: "memory");

    // counter bases (monotonic across replays; read before init gridbar)
    unsigned fb[8];
#pragma unroll
    for (int i = 0; i < 8; i++) fb[i] = *(volatile unsigned*)&g_chk[i * 32];

    // weight slice -> SMEM (bf16, col-major, padded stride)
    for (int e = t; e < 32 * 1024; e += 288) {
        int k = e >> 5, col = e & 31, g = col >> 3, j = col & 7;
        Ws[col * WS_LD + k] = __float2bfloat16(Wg[g][(size_t)k * HH + u0 + j]);
    }
    // zero own 8 rows of hT buffer 0 (8 rows x 256B; 256 threads x 8B)
    if (t < 256)
        *(unsigned long long*)(g_hT2[0] + (u0 + (t >> 5)) * 256 + (t & 31) * 8) = 0ull;

    // ---- fragment-mapped epilogue constants (threads 0..255) ----
    const int r  = w * 16 + (l >> 2);
    const int b1 = r + 8;
    const int uA = u0 + 2 * (l & 3);
    const int uB = uA + 1;
    float2 bF = make_float2(0.f, 0.f), bI = bF, bG = bF, bO = bF;
    if (t < 256) {
        bF = *(const float2*)(bfp + uA);
        bI = *(const float2*)(bip + uA);
        bG = *(const float2*)(bgp + uA);
        bO = *(const float2*)(bop + uA);
    }
    float C0 = 0.f, C1 = 0.f, C2 = 0.f, C3 = 0.f;

    // ldmatrix lane constants (warps 0-7)
    const unsigned a_sw   = (((unsigned)(2 * w + ((l >> 3) & 1)) ^ (unsigned)(l & 7)) << 4);
    const int      a_krow = (l & 7) + ((l >> 4) & 1) * 8;
    const unsigned bbase  = smem0 + SM_WS + ((l & 7) + ((l >> 4) & 1) * 8) * (WS_LD * 2) + ((l >> 3) & 1) * 16;

    // h-store swizzled addresses (4 elements)
    const unsigned hadr0 = (unsigned)(uA * 256 + ((((unsigned)r  >> 3) ^ (uA & 7)) << 4) + (r  & 7) * 2);
    const unsigned hadr1 = (unsigned)(uB * 256 + ((((unsigned)r  >> 3) ^ (uB & 7)) << 4) + (r  & 7) * 2);
    const unsigned hadr2 = (unsigned)(uA * 256 + ((((unsigned)b1 >> 3) ^ (uA & 7)) << 4) + (b1 & 7) * 2);
    const unsigned hadr3 = (unsigned)(uB * 256 + ((((unsigned)b1 >> 3) ^ (uB & 7)) << 4) + (b1 & 7) * 2);

    __syncthreads();
    gridbar();   // zeros + SMEM + mbarriers + counter bases consistent everywhere

    if (t >= 256) {
        // ---------------- producer warp ----------------
        if (t == 256) {
            unsigned q = 0;
            for (int s = 0; s < SS; s++) {
                const unsigned char* hsrc = g_hT2[s & 1];
                const unsigned lvl = (unsigned)s * 128u;   // 16 CTAs x 8 warps per chunk
                for (int cc = 0; cc < 8; cc++, q++) {
                    const int b = q & 3;
                    const unsigned j = q >> 2;
                    if (j) mbar_wait(mbE[b], (j - 1) & 1);    // buffer free
                    if (s) {                                   // producers of chunk cc done step s-1
                        unsigned tgt = fb[cc] + lvl;
                        while ((int)(ld_acq(&g_chk[cc * 32]) - tgt) < 0) { }
                    }
                    mbar_expect(mbF[b], CHUNK_B);
                    bulk_g2s(Abuf[b], hsrc + cc * CHUNK_B, CHUNK_B, mbF[b]);
                }
            }
        }
    } else {
        // ---------------- compute warps (0-7), barrier-free ----------------
        unsigned q = 0;
        for (int s = 0; s < SS; s++) {
            unsigned char* hdst = g_hT2[(s + 1) & 1];

            // gather input-side preacts from E' (L2-resident) + reset masks
            const int xv0 = x[r  * SS + s];
            const int xv1 = x[b1 * SS + s];
            const float* PbA = g_Ep + (size_t)xv0 * 4096 + uA;
            const float* PbB = g_Ep + (size_t)xv1 * 4096 + uA;
            float2 pF0 = *(const float2*)(PbA);
            float2 pI0 = *(const float2*)(PbA + 1024);
            float2 pG0 = *(const float2*)(PbA + 2048);
            float2 pO0 = *(const float2*)(PbA + 3072);
            float2 pF1 = *(const float2*)(PbB);
            float2 pI1 = *(const float2*)(PbB + 1024);
            float2 pG1 = *(const float2*)(PbB + 2048);
            float2 pO1 = *(const float2*)(PbB + 3072);
            const float rm0 = (xv0 > 0) ? 1.0f : 0.0f;
            const float rm1 = (xv1 > 0) ? 1.0f : 0.0f;

            float acc[16];
#pragma unroll
            for (int i = 0; i < 16; i++) acc[i] = 0.0f;

            for (int cc = 0; cc < 8; cc++, q++) {
                const int b = q & 3;
                mbar_wait(mbF[b], (q >> 2) & 1);
                const unsigned Ab = Abuf[b];
#pragma unroll
                for (int kt = 0; kt < 8; kt++) {
                    unsigned aaddr = Ab + (unsigned)((kt * 16 + a_krow) * 256) + a_sw;
                    unsigned a0, a1, a2, a3;
                    asm volatile("ldmatrix.sync.aligned.m8n8.x4.trans.shared.b16 {%0,%1,%2,%3}, [%4];"
                                 : "=r"(a0), "=r"(a1), "=r"(a2), "=r"(a3) : "r"(aaddr));
                    unsigned baddr = bbase + (unsigned)((cc * 8 + kt) * 32);
                    unsigned b0r, b1r, b2r, b3r, b4r, b5r, b6r, b7r;
                    asm volatile("ldmatrix.sync.aligned.m8n8.x4.shared.b16 {%0,%1,%2,%3}, [%4];"
                                 : "=r"(b0r), "=r"(b1r), "=r"(b2r), "=r"(b3r) : "r"(baddr));
                    asm volatile("ldmatrix.sync.aligned.m8n8.x4.shared.b16 {%0,%1,%2,%3}, [%4];"
                                 : "=r"(b4r), "=r"(b5r), "=r"(b6r), "=r"(b7r) : "r"(baddr + 16u * (WS_LD * 2)));

#define MMA4(O, B0, B1) \
                    asm volatile("mma.sync.aligned.m16n8k16.row.col.f32.bf16.bf16.f32 " \
                                 "{%0,%1,%2,%3}, {%4,%5,%6,%7}, {%8,%9}, {%0,%1,%2,%3};" \
                                 : "+f"(acc[O]), "+f"(acc[O+1]), "+f"(acc[O+2]), "+f"(acc[O+3]) \
                                 : "r"(a0), "r"(a1), "r"(a2), "r"(a3), "r"(B0), "r"(B1))
                    MMA4(0,  b0r, b1r);
                    MMA4(4,  b2r, b3r);
                    MMA4(8,  b4r, b5r);
                    MMA4(12, b6r, b7r);
#undef MMA4
                }
                if (l == 0) mbar_arrive(mbE[b]);   // warp done reading buffer b
            }

            // register-resident gate epilogue (approx transcendentals)
            float f, ii, gg, oo, hv0, hv1, hv2, hv3;

            f  = fsigm(pF0.x + bF.x + acc[0]);
            ii = fsigm(pI0.x + bI.x + acc[4]);
            gg = fsigm(pG0.x + bG.x + acc[8]);
            oo = fsigm(pO0.x + bO.x + acc[12]);
            C0 = (gg * ii + C0 * f) * rm0;  hv0 = oo * ftanh(C0);

            f  = fsigm(pF0.y + bF.y + acc[1]);
            ii = fsigm(pI0.y + bI.y + acc[5]);
            gg = fsigm(pG0.y + bG.y + acc[9]);
            oo = fsigm(pO0.y + bO.y + acc[13]);
            C1 = (gg * ii + C1 * f) * rm0;  hv1 = oo * ftanh(C1);

            f  = fsigm(pF1.x + bF.x + acc[2]);
            ii = fsigm(pI1.x + bI.x + acc[6]);
            gg = fsigm(pG1.x + bG.x + acc[10]);
            oo = fsigm(pO1.x + bO.x + acc[14]);
            C2 = (gg * ii + C2 * f) * rm1;  hv2 = oo * ftanh(C2);

            f  = fsigm(pF1.y + bF.y + acc[3]);
            ii = fsigm(pI1.y + bI.y + acc[7]);
            gg = fsigm(pG1.y + bG.y + acc[11]);
            oo = fsigm(pO1.y + bO.y + acc[15]);
            C3 = (gg * ii + C3 * f) * rm1;  hv3 = oo * ftanh(C3);

            *(__nv_bfloat16*)(hdst + hadr0) = __float2bfloat16(hv0);
            *(__nv_bfloat16*)(hdst + hadr1) = __float2bfloat16(hv1);
            *(__nv_bfloat16*)(hdst + hadr2) = __float2bfloat16(hv2);
            *(__nv_bfloat16*)(hdst + hadr3) = __float2bfloat16(hv3);

            if (s == SS - 1) {
                g_hf[r  * HH + uA] = hv0;
                g_hf[r  * HH + uB] = hv1;
                g_hf[b1 * HH + uA] = hv2;
                g_hf[b1 * HH + uB] = hv3;
            }

            // per-warp publish: warp's h stores done -> release-add on own chunk counter
            __syncwarp();
            if (l == 0 && s < SS - 1)
                red_release_add(&g_chk[grp * 32], 1u);
        }
    }
}

// ======================================================================
// Kernel 3: logits + log_softmax — 512 thr, split-K x4, 4 accums each.
// ======================================================================
__global__ __launch_bounds__(512) void k_final(
    const float* __restrict__ Wph, const float* __restrict__ bp,
    float* __restrict__ out)
{
    __shared__ float h[HH];
    __shared__ float part[3][NCC];
    __shared__ float red[NCC];
    const int b = blockIdx.x, t = threadIdx.x;
    const int cls = t & 127, quarter = t >> 7;

    for (int i = t; i < HH; i += 512) h[i] = g_hf[b * HH + i];
    __syncthreads();

    const float* W = Wph + (size_t)(quarter * 256) * NCC + cls;
    const float* hh = h + quarter * 256;
    float a0 = 0.f, a1 = 0.f, a2 = 0.f, a3 = 0.f;
#pragma unroll 8
    for (int k = 0; k < 256; k += 4) {
        a0 += hh[k + 0] * W[(size_t)(k + 0) * NCC];
        a1 += hh[k + 1] * W[(size_t)(k + 1) * NCC];
        a2 += hh[k + 2] * W[(size_t)(k + 2) * NCC];
        a3 += hh[k + 3] * W[(size_t)(k + 3) * NCC];
    }
    float p = (a0 + a1) + (a2 + a3);
    if (quarter) part[quarter - 1][cls] = p;
    __syncthreads();

    if (quarter == 0)
        p += part[0][cls] + part[1][cls] + part[2][cls] + bp[cls];

    if (t < 128) red[t] = p;
    __syncthreads();
    for (int off = 64; off; off >>= 1) {
        if (t < off) red[t] = fmaxf(red[t], red[t + off]);
        __syncthreads();
    }
    float m = red[0]; __syncthreads();
    if (t < 128) red[t] = expf(p - m);
    __syncthreads();
    for (int off = 64; off; off >>= 1) {
        if (t < off) red[t] += red[t + off];
        __syncthreads();
    }
    if (t < 128) {
        float lse = m + logf(red[0]);
        out[b * NCC + t] = p - lse;
    }
}

// ======================================================================
extern "C" void kernel_launch(void* const* d_in, const int* in_sizes, int n_in,
                              void* d_out, int out_size)
{
    const int*   x   = (const int*)  d_in[0];
    const float* emb = (const float*)d_in[1];
    const float* Wfx = (const float*)d_in[2];
    const float* Wfh = (const float*)d_in[3];
    const float* bf  = (const float*)d_in[4];
    const float* Wix = (const float*)d_in[5];
    const float* Wih = (const float*)d_in[6];
    const float* bi  = (const float*)d_in[7];
    const float* Wgx = (const float*)d_in[8];
    const float* Wgh = (const float*)d_in[9];
    const float* bg  = (const float*)d_in[10];
    const float* Wox = (const float*)d_in[11];
    const float* Woh = (const float*)d_in[12];
    const float* bo  = (const float*)d_in[13];
    const float* Wph = (const float*)d_in[14];
    const float* bp  = (const float*)d_in[15];
    float* out = (float*)d_out;

    const int eprime_smem = 512 * 32 * 4;   // 64 KB
    static bool attr_set = false;
    if (!attr_set) {
        cudaFuncSetAttribute(k_eprime, cudaFuncAttributeMaxDynamicSharedMemorySize, eprime_smem);
        cudaFuncSetAttribute(k_recur,  cudaFuncAttributeMaxDynamicSharedMemorySize, SM_TOT);
        attr_set = true;
    }

    // 1) E' = emb @ [Wfx|Wix|Wgx|Wox]  (129 x 4096, fp32, replaces the big input GEMM)
    k_eprime<<<128, 256, eprime_smem>>>(emb, Wfx, Wix, Wgx, Wox);

    // 2) persistent recurrent scan (warp-specialized, barrier-free loop)
    k_recur<<<NCTA_REC, 288, SM_TOT>>>(x, Wfh, Wih, Wgh, Woh, bf, bi, bg, bo);

    // 3) final projection + log_softmax
    k_final<<<BB, 512>>>(Wph, bp, out);
}